// round 1
// baseline (speedup 1.0000x reference)
#include <cuda_runtime.h>

// Problem constants (fixed shapes from reference)
#define B   4
#define NB  2048
#define BS  32
#define D   256
#define NF  512
#define NC  1024
#define D4  (D/4)          // 64 float4 per row

// ---------------------------------------------------------------------------
// Kernel 1: partial_fine_token_states [B, NF*BS, D]
//   out[b, f*BS+s, :] = coarse_states[b, fidx, :] - cache_bank[b, table[b,fidx], s, :]
// One thread per float4.  Total = B*NF*BS*D4 = 4*512*32*64 = 2^22 threads.
// Index decode via bit ops (all dims powers of two).
// ---------------------------------------------------------------------------
__global__ void fine_states_kernel(const float4* __restrict__ coarse,      // [B,NB,D]
                                   const float4* __restrict__ bank,        // [B,NB,BS,D]
                                   const int*    __restrict__ fidx,        // [B,NF]
                                   const int*    __restrict__ table,       // [B,NB]
                                   float4*       __restrict__ out)         // [B,NF*BS,D]
{
    unsigned i  = blockIdx.x * blockDim.x + threadIdx.x;   // < 2^22
    unsigned d4 = i & 63u;           // D4-1
    unsigned s  = (i >> 6) & 31u;    // BS-1
    unsigned f  = (i >> 11) & 511u;  // NF-1
    unsigned b  = i >> 20;           // B

    int fi = __ldg(&fidx[b * NF + f]);
    int bi = __ldg(&table[b * NB + fi]);

    float4 c = coarse[(b * NB + (unsigned)fi) * (unsigned)D4 + d4];
    float4 v = bank[(((b * NB + (unsigned)bi) * (unsigned)BS) + s) * (unsigned)D4 + d4];

    out[i] = make_float4(c.x - v.x, c.y - v.y, c.z - v.z, c.w - v.w);
}

// ---------------------------------------------------------------------------
// Kernel 2: partial_coarse_token_states [B, NC, D]
//   out[b, c, :] = coarse_states[b, cidx[b,c], :]
// Total = B*NC*D4 = 4*1024*64 = 2^18 threads.
// ---------------------------------------------------------------------------
__global__ void coarse_states_kernel(const float4* __restrict__ coarse,    // [B,NB,D]
                                     const int*    __restrict__ cidx,      // [B,NC]
                                     float4*       __restrict__ out)       // [B,NC,D]
{
    unsigned i  = blockIdx.x * blockDim.x + threadIdx.x;   // < 2^18
    unsigned d4 = i & 63u;            // D4-1
    unsigned c  = (i >> 6) & 1023u;   // NC-1
    unsigned b  = i >> 16;            // B

    int ci = __ldg(&cidx[b * NC + c]);
    out[i] = coarse[(b * NB + (unsigned)ci) * (unsigned)D4 + d4];
}

// ---------------------------------------------------------------------------
// Kernel 3: all scalar outputs.
//   fine_mask  [B,NF*BS] : ftm[b, fidx*BS + s]
//   fine_score [B,NF*BS] : fscore[b,f] broadcast
//   fine_dups  [B,NF*BS] : 1.0
//   coarse_mask  [B,NC]  : ctm[b, cidx]
//   coarse_score [B,NC]  : cscore copy
//   coarse_dups  [B,NC]  : 32.0
// 65536 threads; first 4096 also handle coarse scalars.
// ---------------------------------------------------------------------------
__global__ void scalars_kernel(const float* __restrict__ ftm,     // [B, NB*BS]
                               const int*   __restrict__ fidx,    // [B, NF]
                               const float* __restrict__ fscore,  // [B, NF]
                               const float* __restrict__ ctm,     // [B, NB]
                               const int*   __restrict__ cidx,    // [B, NC]
                               const float* __restrict__ cscore,  // [B, NC]
                               float* __restrict__ fine_mask,
                               float* __restrict__ fine_score_o,
                               float* __restrict__ fine_dups,
                               float* __restrict__ coarse_mask,
                               float* __restrict__ coarse_score_o,
                               float* __restrict__ coarse_dups)
{
    unsigned i = blockIdx.x * blockDim.x + threadIdx.x;   // < 65536
    unsigned s = i & 31u;          // BS-1
    unsigned f = (i >> 5) & 511u;  // NF-1
    unsigned b = i >> 14;          // B

    int fi = __ldg(&fidx[b * NF + f]);
    fine_mask[i]    = __ldg(&ftm[b * (NB * BS) + (unsigned)fi * BS + s]);
    fine_score_o[i] = __ldg(&fscore[b * NF + f]);
    fine_dups[i]    = 1.0f;

    if (i < (unsigned)(B * NC)) {
        unsigned c  = i & 1023u;   // NC-1
        unsigned b2 = i >> 10;
        int ci = __ldg(&cidx[b2 * NC + c]);
        coarse_mask[i]    = __ldg(&ctm[b2 * NB + (unsigned)ci]);
        coarse_score_o[i] = __ldg(&cscore[i]);
        coarse_dups[i]    = 32.0f;
    }
}

extern "C" void kernel_launch(void* const* d_in, const int* in_sizes, int n_in,
                              void* d_out, int out_size)
{
    // Input order per metadata:
    const float* fine_token_mask     = (const float*)d_in[0];  // [B, NB*BS]
    const float* coarse_token_states = (const float*)d_in[1];  // [B, NB, D]
    const float* coarse_token_mask   = (const float*)d_in[2];  // [B, NB]
    const int*   fine_block_indices  = (const int*)  d_in[3];  // [B, NF]
    const float* fine_block_scores   = (const float*)d_in[4];  // [B, NF]
    const int*   coarse_block_indices= (const int*)  d_in[5];  // [B, NC]
    const float* coarse_block_scores = (const float*)d_in[6];  // [B, NC]
    const int*   cache_indice_table  = (const int*)  d_in[7];  // [B, NB]
    const float* cache_bank          = (const float*)d_in[8];  // [B, NB, BS, D]

    float* out = (float*)d_out;

    // Flat output layout (return order)
    const long long n_fine_states   = (long long)B * NF * BS * D;   // 16,777,216
    const long long n_fine_scalar   = (long long)B * NF * BS;       // 65,536
    const long long n_coarse_states = (long long)B * NC * D;        // 1,048,576
    const long long n_coarse_scalar = (long long)B * NC;            // 4,096

    float* o_fine_states   = out;
    float* o_fine_mask     = o_fine_states   + n_fine_states;
    float* o_fine_scores   = o_fine_mask     + n_fine_scalar;
    float* o_fine_dups     = o_fine_scores   + n_fine_scalar;
    float* o_coarse_states = o_fine_dups     + n_fine_scalar;
    float* o_coarse_mask   = o_coarse_states + n_coarse_states;
    float* o_coarse_scores = o_coarse_mask   + n_coarse_scalar;
    float* o_coarse_dups   = o_coarse_scores + n_coarse_scalar;

    // Kernel 1: 2^22 threads
    {
        int threads = 256;
        int blocks  = (B * NF * BS * D4) / threads;   // 16384
        fine_states_kernel<<<blocks, threads>>>(
            (const float4*)coarse_token_states,
            (const float4*)cache_bank,
            fine_block_indices,
            cache_indice_table,
            (float4*)o_fine_states);
    }

    // Kernel 2: 2^18 threads
    {
        int threads = 256;
        int blocks  = (B * NC * D4) / threads;        // 1024
        coarse_states_kernel<<<blocks, threads>>>(
            (const float4*)coarse_token_states,
            coarse_block_indices,
            (float4*)o_coarse_states);
    }

    // Kernel 3: 65536 threads
    {
        int threads = 256;
        int blocks  = (B * NF * BS) / threads;        // 256
        scalars_kernel<<<blocks, threads>>>(
            fine_token_mask, fine_block_indices, fine_block_scores,
            coarse_token_mask, coarse_block_indices, coarse_block_scores,
            o_fine_mask, o_fine_scores, o_fine_dups,
            o_coarse_mask, o_coarse_scores, o_coarse_dups);
    }
}

// round 2
// speedup vs baseline: 1.4349x; 1.4349x over previous
#include <cuda_runtime.h>

// Problem constants (fixed shapes)
#define B   4
#define NB  2048
#define BS  32
#define D   256
#define NF  512
#define NC  1024
#define D4  (D/4)              // 64 float4 per row
#define TILE_F4 (BS * D4)      // 2048 float4 per (b,f) tile = 8 KB

// Grid partition
#define FINE_BLOCKS    (B * NF)                 // 2048  (one CTA per (b,f))
#define COARSE_BLOCKS  ((B * NC * D4) / 256)    // 1024
#define SCALAR_BLOCKS  ((B * NF * BS) / 256)    // 256
#define TOTAL_BLOCKS   (FINE_BLOCKS + COARSE_BLOCKS + SCALAR_BLOCKS)

__global__ void __launch_bounds__(256) fused_kernel(
    const float4* __restrict__ coarse,    // [B,NB,D4]
    const float4* __restrict__ bank,      // [B,NB,BS,D4]
    const int*    __restrict__ fidx,      // [B,NF]
    const int*    __restrict__ table,     // [B,NB]
    const float*  __restrict__ ftm,       // [B, NB*BS]
    const float*  __restrict__ fscore,    // [B, NF]
    const float*  __restrict__ ctm,       // [B, NB]
    const int*    __restrict__ cidx,      // [B, NC]
    const float*  __restrict__ cscore,    // [B, NC]
    float4* __restrict__ o_fine_states,   // [B*NF] tiles of 2048 f4
    float*  __restrict__ o_fine_mask,
    float*  __restrict__ o_fine_scores,
    float*  __restrict__ o_fine_dups,
    float4* __restrict__ o_coarse_states, // [B,NC,D4]
    float*  __restrict__ o_coarse_mask,
    float*  __restrict__ o_coarse_scores,
    float*  __restrict__ o_coarse_dups)
{
    const unsigned bid = blockIdx.x;
    const unsigned t   = threadIdx.x;

    if (bid < FINE_BLOCKS) {
        // ---- fine token states: one 8KB tile per CTA ----
        __shared__ float4 crow[D4];

        const unsigned b = bid >> 9;       // / NF
        const unsigned f = bid & (NF - 1);

        const int fi = __ldg(&fidx[b * NF + f]);
        const int bi = __ldg(&table[b * NB + fi]);

        if (t < D4)
            crow[t] = coarse[(b * NB + (unsigned)fi) * D4 + t];
        __syncthreads();

        const float4* __restrict__ bt = bank + (size_t)(b * NB + (unsigned)bi) * TILE_F4;
        float4*       __restrict__ ot = o_fine_states + (size_t)bid * TILE_F4;

        // 8 independent loads per thread (MLP=8), fully coalesced
        float4 v[8];
        #pragma unroll
        for (int k = 0; k < 8; k++)
            v[k] = bt[k * 256 + t];

        #pragma unroll
        for (int k = 0; k < 8; k++) {
            const unsigned idx = k * 256 + t;
            const float4 c = crow[idx & (D4 - 1)];
            ot[idx] = make_float4(c.x - v[k].x, c.y - v[k].y,
                                  c.z - v[k].z, c.w - v[k].w);
        }
    }
    else if (bid < FINE_BLOCKS + COARSE_BLOCKS) {
        // ---- coarse token states gather ----
        const unsigned i  = (bid - FINE_BLOCKS) * 256 + t;   // < B*NC*D4 = 2^18
        const unsigned d4 = i & (D4 - 1);
        const unsigned c  = (i >> 6) & (NC - 1);
        const unsigned b  = i >> 16;

        const int ci = __ldg(&cidx[b * NC + c]);
        o_coarse_states[i] = coarse[(b * NB + (unsigned)ci) * D4 + d4];
    }
    else {
        // ---- all scalar outputs ----
        const unsigned i = (bid - FINE_BLOCKS - COARSE_BLOCKS) * 256 + t;  // < 65536
        const unsigned s = i & (BS - 1);
        const unsigned f = (i >> 5) & (NF - 1);
        const unsigned b = i >> 14;

        const int fi = __ldg(&fidx[b * NF + f]);
        o_fine_mask[i]   = __ldg(&ftm[b * (NB * BS) + (unsigned)fi * BS + s]);
        o_fine_scores[i] = __ldg(&fscore[b * NF + f]);
        o_fine_dups[i]   = 1.0f;

        if (i < (unsigned)(B * NC)) {
            const unsigned c  = i & (NC - 1);
            const unsigned b2 = i >> 10;
            const int ci = __ldg(&cidx[b2 * NC + c]);
            o_coarse_mask[i]   = __ldg(&ctm[b2 * NB + (unsigned)ci]);
            o_coarse_scores[i] = __ldg(&cscore[i]);
            o_coarse_dups[i]   = 32.0f;
        }
    }
}

extern "C" void kernel_launch(void* const* d_in, const int* in_sizes, int n_in,
                              void* d_out, int out_size)
{
    const float* fine_token_mask      = (const float*)d_in[0];
    const float* coarse_token_states  = (const float*)d_in[1];
    const float* coarse_token_mask    = (const float*)d_in[2];
    const int*   fine_block_indices   = (const int*)  d_in[3];
    const float* fine_block_scores    = (const float*)d_in[4];
    const int*   coarse_block_indices = (const int*)  d_in[5];
    const float* coarse_block_scores  = (const float*)d_in[6];
    const int*   cache_indice_table   = (const int*)  d_in[7];
    const float* cache_bank           = (const float*)d_in[8];

    float* out = (float*)d_out;

    const long long n_fine_states   = (long long)B * NF * BS * D;   // 16,777,216
    const long long n_fine_scalar   = (long long)B * NF * BS;       // 65,536
    const long long n_coarse_states = (long long)B * NC * D;        // 1,048,576
    const long long n_coarse_scalar = (long long)B * NC;            // 4,096

    float* o_fine_states   = out;
    float* o_fine_mask     = o_fine_states   + n_fine_states;
    float* o_fine_scores   = o_fine_mask     + n_fine_scalar;
    float* o_fine_dups     = o_fine_scores   + n_fine_scalar;
    float* o_coarse_states = o_fine_dups     + n_fine_scalar;
    float* o_coarse_mask   = o_coarse_states + n_coarse_states;
    float* o_coarse_scores = o_coarse_mask   + n_coarse_scalar;
    float* o_coarse_dups   = o_coarse_scores + n_coarse_scalar;

    fused_kernel<<<TOTAL_BLOCKS, 256>>>(
        (const float4*)coarse_token_states,
        (const float4*)cache_bank,
        fine_block_indices,
        cache_indice_table,
        fine_token_mask,
        fine_block_scores,
        coarse_token_mask,
        coarse_block_indices,
        coarse_block_scores,
        (float4*)o_fine_states,
        o_fine_mask, o_fine_scores, o_fine_dups,
        (float4*)o_coarse_states,
        o_coarse_mask, o_coarse_scores, o_coarse_dups);
}